// round 2
// baseline (speedup 1.0000x reference)
#include <cuda_runtime.h>
#include <cstdint>

// Problem constants (static shapes from reference)
#define CC   64          // channels
#define CINN 66          // channels + 2 coord planes
#define HH   160
#define WW   256
#define LL   (HH * WW)   // 40960 pixels
#define TP   128         // pixels per tile
#define NINST 32         // 4 images * 8 instances
#define NPARAMS 8513

// param layout offsets
#define OFF_W0 0
#define OFF_W1 4224
#define OFF_W2 8320
#define OFF_B0 8384
#define OFF_B1 8448
#define OFF_B2 8512
#define MASK_BIAS_SHIFT 2.19f

// smem layout (floats) — every section base is a multiple of 4 floats (16B)
//  sW0 : [k][o] k<66, stride 65   -> 4290, padded to 4292
//  sW1 : [k][o] k<64, stride 65   -> 4160
//  sX  : [k][p] k<66, stride 128  -> 8448   (base 8452: 16B aligned)
//  sH  : [o][p] o<64, stride 132  -> 8448   (base 16900: 16B aligned)
//  sw2/sb0/sb1 : 64 each, sb2 : 1 -> 193
#define SW0_STRIDE 65
#define SW0_SIZE   4292      // 66*65 = 4290, +2 pad for 16B alignment of next section
#define SW1_STRIDE 65
#define SX_STRIDE  128
#define SH_STRIDE  132
#define SMEM_FLOATS (SW0_SIZE + 64*65 + 66*128 + 64*132 + 193)
#define SMEM_BYTES  (SMEM_FLOATS * 4)

__device__ __forceinline__ unsigned long long pack2(float a, float b) {
    unsigned long long r;
    asm("mov.b64 %0, {%1,%2};" : "=l"(r) : "f"(a), "f"(b));
    return r;
}
__device__ __forceinline__ void fma2(unsigned long long& d, unsigned long long a, unsigned long long b) {
    asm("fma.rn.f32x2 %0, %1, %2, %0;" : "+l"(d) : "l"(a), "l"(b));
}
__device__ __forceinline__ float2 unpack2(unsigned long long v) {
    float2 f;
    asm("mov.b64 {%0,%1}, %2;" : "=f"(f.x), "=f"(f.y) : "l"(v));
    return f;
}

extern __shared__ __align__(16) float smem[];

__global__ __launch_bounds__(256, 2)
void condlane_fused_kernel(const float* __restrict__ x,
                           const float* __restrict__ params,
                           float* __restrict__ out)
{
    float* sW0 = smem;                       // 66 * 65 (+2 pad)
    float* sW1 = sW0 + SW0_SIZE;             // 64 * 65
    float* sX  = sW1 + 64 * SW1_STRIDE;      // 66 * 128   base 8452 (16B aligned)
    float* sH  = sX  + 66 * SX_STRIDE;       // 64 * 132   base 16900 (16B aligned)
    float* sw2 = sH  + 64 * SH_STRIDE;       // 64
    float* sb0 = sw2 + 64;                   // 64
    float* sb1 = sb0 + 64;                   // 64
    float* sb2 = sb1 + 64;                   // 1

    const int tile = blockIdx.x;   // 0..319
    const int inst = blockIdx.y;   // 0..31
    const int img  = inst >> 3;    // 8 instances per image (static num_ins)
    const int tid  = threadIdx.x;

    const float* p = params + (size_t)inst * NPARAMS;

    // ---- load W0 [64][66] -> sW0[c][o] (transposed, padded stride) ----
    for (int idx = tid; idx < 64 * 66; idx += 256) {
        int o = idx / 66;
        int c = idx - o * 66;
        sW0[c * SW0_STRIDE + o] = p[OFF_W0 + idx];
    }
    // ---- load W1 [64][64] -> sW1[c][o] ----
    for (int idx = tid; idx < 64 * 64; idx += 256) {
        int o = idx >> 6;
        int c = idx & 63;
        sW1[c * SW1_STRIDE + o] = p[OFF_W1 + idx];
    }
    if (tid < 64) {
        sw2[tid] = p[OFF_W2 + tid];
        sb0[tid] = p[OFF_B0 + tid];
        sb1[tid] = p[OFF_B1 + tid];
    }
    if (tid == 0) sb2[0] = p[OFF_B2] - MASK_BIAS_SHIFT;

    // ---- build X tile [66][128]: rows 0,1 coords, rows 2..65 = image channels ----
    const int l0 = tile * TP;            // tile start pixel
    const int ycoord = l0 / WW;          // constant over the tile (TP divides WW)
    const int xbase0 = l0 - ycoord * WW; // 0 or 128
    if (tid < 64) {
        int row = tid >> 5;              // 0: x-coords, 1: y-coords
        int c4  = (tid & 31) * 4;
        float4 v;
        if (row == 0) {
            float xb = (float)(xbase0 + c4);
            v = make_float4(xb, xb + 1.f, xb + 2.f, xb + 3.f);
        } else {
            float yf = (float)ycoord;
            v = make_float4(yf, yf, yf, yf);
        }
        *(float4*)(sX + row * SX_STRIDE + c4) = v;
    }
    {
        const float* xb = x + (size_t)img * CC * LL + l0;
        int r  = tid >> 5;               // 0..7
        int c4 = (tid & 31) * 4;         // 0..124
        #pragma unroll
        for (int i = 0; i < 8; i++) {
            int ch = i * 8 + r;
            float4 v = *(const float4*)(xb + (size_t)ch * LL + c4);
            *(float4*)(sX + (2 + ch) * SX_STRIDE + c4) = v;
        }
    }
    __syncthreads();

    // ---- thread tile: 4 output rows x 8 pixels (two groups of 4 consecutive) ----
    const int tr = tid >> 4;      // 0..15 -> rows tr*4..tr*4+3
    const int tc = tid & 15;      // 0..15 -> cols tc*4..+3 and 64+tc*4..+3
    const int ro = tr * 4;
    const int co = tc * 4;

    unsigned long long acc[4][4];
    #pragma unroll
    for (int i = 0; i < 4; i++)
        #pragma unroll
        for (int j = 0; j < 4; j++) acc[i][j] = 0ULL;

    // ======== GEMM1: hdn0 = W0 @ X  (K = 66) ========
    #pragma unroll 2
    for (int k = 0; k < CINN; k++) {
        ulonglong2 xa  = *(const ulonglong2*)(sX + k * SX_STRIDE + co);
        ulonglong2 xbv = *(const ulonglong2*)(sX + k * SX_STRIDE + 64 + co);
        unsigned long long xp0 = xa.x, xp1 = xa.y, xp2 = xbv.x, xp3 = xbv.y;
        const float* wk = sW0 + k * SW0_STRIDE + ro;
        #pragma unroll
        for (int i = 0; i < 4; i++) {
            unsigned long long wp = pack2(wk[i], wk[i]);
            fma2(acc[i][0], wp, xp0);
            fma2(acc[i][1], wp, xp1);
            fma2(acc[i][2], wp, xp2);
            fma2(acc[i][3], wp, xp3);
        }
    }

    // bias + relu -> sH
    #pragma unroll
    for (int i = 0; i < 4; i++) {
        float b = sb0[ro + i];
        float r[8];
        float2 t;
        t = unpack2(acc[i][0]); r[0] = t.x; r[1] = t.y;
        t = unpack2(acc[i][1]); r[2] = t.x; r[3] = t.y;
        t = unpack2(acc[i][2]); r[4] = t.x; r[5] = t.y;
        t = unpack2(acc[i][3]); r[6] = t.x; r[7] = t.y;
        #pragma unroll
        for (int j = 0; j < 8; j++) {
            r[j] += b;
            r[j] = r[j] > 0.f ? r[j] : 0.f;
        }
        *(float4*)(sH + (ro + i) * SH_STRIDE + co)      = make_float4(r[0], r[1], r[2], r[3]);
        *(float4*)(sH + (ro + i) * SH_STRIDE + 64 + co) = make_float4(r[4], r[5], r[6], r[7]);
    }
    __syncthreads();

    // ======== GEMM2: hdn1 = W1 @ relu(hdn0)  (K = 64) ========
    #pragma unroll
    for (int i = 0; i < 4; i++)
        #pragma unroll
        for (int j = 0; j < 4; j++) acc[i][j] = 0ULL;

    #pragma unroll 2
    for (int k = 0; k < CC; k++) {
        ulonglong2 xa  = *(const ulonglong2*)(sH + k * SH_STRIDE + co);
        ulonglong2 xbv = *(const ulonglong2*)(sH + k * SH_STRIDE + 64 + co);
        unsigned long long xp0 = xa.x, xp1 = xa.y, xp2 = xbv.x, xp3 = xbv.y;
        const float* wk = sW1 + k * SW1_STRIDE + ro;
        #pragma unroll
        for (int i = 0; i < 4; i++) {
            unsigned long long wp = pack2(wk[i], wk[i]);
            fma2(acc[i][0], wp, xp0);
            fma2(acc[i][1], wp, xp1);
            fma2(acc[i][2], wp, xp2);
            fma2(acc[i][3], wp, xp3);
        }
    }
    __syncthreads();   // all reads of sH done before overwrite

    // bias + relu -> sH (reuse)
    #pragma unroll
    for (int i = 0; i < 4; i++) {
        float b = sb1[ro + i];
        float r[8];
        float2 t;
        t = unpack2(acc[i][0]); r[0] = t.x; r[1] = t.y;
        t = unpack2(acc[i][1]); r[2] = t.x; r[3] = t.y;
        t = unpack2(acc[i][2]); r[4] = t.x; r[5] = t.y;
        t = unpack2(acc[i][3]); r[6] = t.x; r[7] = t.y;
        #pragma unroll
        for (int j = 0; j < 8; j++) {
            r[j] += b;
            r[j] = r[j] > 0.f ? r[j] : 0.f;
        }
        *(float4*)(sH + (ro + i) * SH_STRIDE + co)      = make_float4(r[0], r[1], r[2], r[3]);
        *(float4*)(sH + (ro + i) * SH_STRIDE + 64 + co) = make_float4(r[4], r[5], r[6], r[7]);
    }
    __syncthreads();

    // ======== Layer 3: out[p] = w2 . hdn1[:,p] + b2 ========
    if (tid < TP) {
        float a3 = sb2[0];
        #pragma unroll
        for (int o = 0; o < CC; o++)
            a3 = fmaf(sw2[o], sH[o * SH_STRIDE + tid], a3);
        out[(size_t)inst * LL + l0 + tid] = a3;
    }
}

extern "C" void kernel_launch(void* const* d_in, const int* in_sizes, int n_in,
                              void* d_out, int out_size)
{
    const float* x      = (const float*)d_in[0];   // [4,64,160,256] fp32
    const float* params = (const float*)d_in[1];   // [32,8513] fp32
    // d_in[2] = num_ins (static 8 per image, unused)
    float* out = (float*)d_out;                    // [1,32,160,256] fp32

    (void)in_sizes; (void)n_in; (void)out_size;

    cudaFuncSetAttribute(condlane_fused_kernel,
                         cudaFuncAttributeMaxDynamicSharedMemorySize, SMEM_BYTES);

    dim3 grid(LL / TP, NINST);   // 320 x 32
    condlane_fused_kernel<<<grid, 256, SMEM_BYTES>>>(x, params, out);
}